// round 5
// baseline (speedup 1.0000x reference)
#include <cuda_runtime.h>

// Problem: B=16, S=4096.
// predicted_start[b] = argmax_s ( start[b,s] * max_{t>=s} end[b,t] )
// predicted_end[b]   = argmax_t ( end[b,t]   * max_{s<=t} start[b,s] )
// argmax = first occurrence (jnp semantics).

#define SB  16
#define SS  4096
#define NT  256
#define VPT 16          // elements per thread (4 float4 loads per array)
#define NW  (NT / 32)   // 8 warps

__global__ __launch_bounds__(NT, 1)
void probs_to_span_kernel(const float* __restrict__ start_p,
                          const float* __restrict__ end_p,
                          float* __restrict__ out)
{
    const int b    = blockIdx.x;
    const int tid  = threadIdx.x;
    const int wid  = tid >> 5;
    const int lane = tid & 31;
    const float NEG = -3.0e38f;

    const float4* sp = reinterpret_cast<const float4*>(start_p + (size_t)b * SS);
    const float4* ep = reinterpret_cast<const float4*>(end_p   + (size_t)b * SS);

    // Front-batched loads: 8 independent LDG.128 in flight.
    float4 s4[4], e4[4];
    #pragma unroll
    for (int j = 0; j < 4; j++) s4[j] = sp[tid * 4 + j];
    #pragma unroll
    for (int j = 0; j < 4; j++) e4[j] = ep[tid * 4 + j];

    float st[VPT], en[VPT];
    #pragma unroll
    for (int j = 0; j < 4; j++) {
        st[4*j+0] = s4[j].x; st[4*j+1] = s4[j].y; st[4*j+2] = s4[j].z; st[4*j+3] = s4[j].w;
        en[4*j+0] = e4[j].x; en[4*j+1] = e4[j].y; en[4*j+2] = e4[j].z; en[4*j+3] = e4[j].w;
    }

    // Chunk maxima.
    float cs = NEG, ce = NEG;
    #pragma unroll
    for (int i = 0; i < VPT; i++) { cs = fmaxf(cs, st[i]); ce = fmaxf(ce, en[i]); }

    // Warp-level inclusive prefix-max of cs (ascending lanes) and
    // inclusive suffix-max of ce (descending lanes), via shuffles.
    float ps = cs;
    #pragma unroll
    for (int off = 1; off < 32; off <<= 1) {
        float o = __shfl_up_sync(0xffffffffu, ps, off);
        if (lane >= off) ps = fmaxf(ps, o);
    }
    float se = ce;
    #pragma unroll
    for (int off = 1; off < 32; off <<= 1) {
        float o = __shfl_down_sync(0xffffffffu, se, off);
        if (lane + off < 32) se = fmaxf(se, o);
    }

    // Cross-warp totals (warp total of start prefix = ps at lane 31,
    // warp total of end suffix = se at lane 0).
    __shared__ float wS[NW], wE[NW];
    if (lane == 31) wS[wid] = ps;
    if (lane == 0)  wE[wid] = se;
    __syncthreads();

    float warpPrevS = NEG, warpNextE = NEG;
    #pragma unroll
    for (int w = 0; w < NW; w++) {
        float vS = wS[w], vE = wE[w];
        if (w < wid) warpPrevS = fmaxf(warpPrevS, vS);
        if (w > wid) warpNextE = fmaxf(warpNextE, vE);
    }

    // Exclusive-within-warp boundary values.
    float exS = __shfl_up_sync(0xffffffffu, ps, 1);
    if (lane == 0) exS = NEG;
    float exE = __shfl_down_sync(0xffffffffu, se, 1);
    if (lane == 31) exE = NEG;

    float pm = fmaxf(warpPrevS, exS);  // max start over indices <  tid*VPT
    float sm = fmaxf(warpNextE, exE);  // max end   over indices >  tid*VPT+15

    // predicted_end candidate: v2[t] = end[t] * prefixmax_start[t], ascending, '>' keeps first.
    float bestv2 = NEG; int besti2 = 0;
    float p = pm;
    #pragma unroll
    for (int i = 0; i < VPT; i++) {
        p = fmaxf(p, st[i]);
        float v = en[i] * p;
        if (v > bestv2) { bestv2 = v; besti2 = tid * VPT + i; }
    }

    // predicted_start candidate: v1[s] = start[s] * suffixmax_end[s], descending, '>=' keeps smallest.
    float bestv1 = NEG; int besti1 = 0;
    float q = sm;
    #pragma unroll
    for (int i = VPT - 1; i >= 0; i--) {
        q = fmaxf(q, en[i]);
        float v = st[i] * q;
        if (v >= bestv1) { bestv1 = v; besti1 = tid * VPT + i; }
    }

    // Warp argmax reductions (max value, min index on ties).
    #pragma unroll
    for (int off = 16; off > 0; off >>= 1) {
        float ov1 = __shfl_down_sync(0xffffffffu, bestv1, off);
        int   oi1 = __shfl_down_sync(0xffffffffu, besti1, off);
        if (ov1 > bestv1 || (ov1 == bestv1 && oi1 < besti1)) { bestv1 = ov1; besti1 = oi1; }
        float ov2 = __shfl_down_sync(0xffffffffu, bestv2, off);
        int   oi2 = __shfl_down_sync(0xffffffffu, besti2, off);
        if (ov2 > bestv2 || (ov2 == bestv2 && oi2 < besti2)) { bestv2 = ov2; besti2 = oi2; }
    }

    __shared__ float rv1[NW], rv2[NW];
    __shared__ int   ri1[NW], ri2[NW];
    if (lane == 0) { rv1[wid] = bestv1; ri1[wid] = besti1; rv2[wid] = bestv2; ri2[wid] = besti2; }
    __syncthreads();

    if (tid == 0) {
        float v1 = rv1[0]; int i1 = ri1[0];
        float v2 = rv2[0]; int i2 = ri2[0];
        #pragma unroll
        for (int w = 1; w < NW; w++) {
            if (rv1[w] > v1 || (rv1[w] == v1 && ri1[w] < i1)) { v1 = rv1[w]; i1 = ri1[w]; }
            if (rv2[w] > v2 || (rv2[w] == v2 && ri2[w] < i2)) { v2 = rv2[w]; i2 = ri2[w]; }
        }
        out[b]      = (float)i1;   // predicted_start
        out[SB + b] = (float)i2;   // predicted_end
    }
}

extern "C" void kernel_launch(void* const* d_in, const int* in_sizes, int n_in,
                              void* d_out, int out_size)
{
    const float* start_p = (const float*)d_in[0];
    const float* end_p   = (const float*)d_in[1];
    float* out           = (float*)d_out;
    probs_to_span_kernel<<<SB, NT>>>(start_p, end_p, out);
}

// round 6
// speedup vs baseline: 3.1532x; 3.1532x over previous
#include <cuda_runtime.h>

// Problem: B=16, S=4096.
// predicted_start[b] = argmax_s ( start[b,s] * max_{t>=s} end[b,t] )
// predicted_end[b]   = argmax_t ( end[b,t]   * max_{s<=t} start[b,s] )
// argmax = first occurrence (jnp semantics).

#define SB  16
#define SS  4096
#define NT  1024
#define VPT 4           // one float4 per array per thread, fully coalesced
#define NW  (NT / 32)   // 32 warps

__global__ __launch_bounds__(NT, 1)
void probs_to_span_kernel(const float* __restrict__ start_p,
                          const float* __restrict__ end_p,
                          float* __restrict__ out)
{
    const int b    = blockIdx.x;
    const int tid  = threadIdx.x;
    const int wid  = tid >> 5;
    const int lane = tid & 31;
    const float NEG = -3.0e38f;

    const float4* sp = reinterpret_cast<const float4*>(start_p + (size_t)b * SS);
    const float4* ep = reinterpret_cast<const float4*>(end_p   + (size_t)b * SS);

    // Coalesced: warp covers 512B contiguous per LDG.128 (4 lines/instr).
    float4 s4 = sp[tid];
    float4 e4 = ep[tid];
    float st[VPT] = {s4.x, s4.y, s4.z, s4.w};
    float en[VPT] = {e4.x, e4.y, e4.z, e4.w};

    // Chunk maxima.
    float cs = fmaxf(fmaxf(st[0], st[1]), fmaxf(st[2], st[3]));
    float ce = fmaxf(fmaxf(en[0], en[1]), fmaxf(en[2], en[3]));

    // Warp inclusive prefix-max of cs (ascending) / suffix-max of ce (descending).
    float ps = cs;
    #pragma unroll
    for (int off = 1; off < 32; off <<= 1) {
        float o = __shfl_up_sync(0xffffffffu, ps, off);
        if (lane >= off) ps = fmaxf(ps, o);
    }
    float se = ce;
    #pragma unroll
    for (int off = 1; off < 32; off <<= 1) {
        float o = __shfl_down_sync(0xffffffffu, se, off);
        if (lane + off < 32) se = fmaxf(se, o);
    }

    // Publish warp totals.
    __shared__ float wS[NW], wE[NW];
    if (lane == 31) wS[wid] = ps;   // warp max of start chunk-maxima
    if (lane == 0)  wE[wid] = se;   // warp max of end chunk-maxima
    __syncthreads();

    // Cross-warp exclusive boundaries for this warp.
    float warpPrevS = NEG, warpNextE = NEG;
    #pragma unroll
    for (int w = 0; w < NW; w++) {
        float vS = wS[w], vE = wE[w];
        if (w < wid) warpPrevS = fmaxf(warpPrevS, vS);
        if (w > wid) warpNextE = fmaxf(warpNextE, vE);
    }

    // Exclusive-within-warp boundary values.
    float exS = __shfl_up_sync(0xffffffffu, ps, 1);
    if (lane == 0) exS = NEG;
    float exE = __shfl_down_sync(0xffffffffu, se, 1);
    if (lane == 31) exE = NEG;

    float pm = fmaxf(warpPrevS, exS);  // max start over indices <  tid*VPT
    float sm = fmaxf(warpNextE, exE);  // max end   over indices >  tid*VPT+3

    // predicted_end candidate: v2[t] = end[t] * prefixmax_start[t]; ascending, '>' keeps first.
    float bestv2 = NEG; int besti2 = 0;
    float p = pm;
    #pragma unroll
    for (int i = 0; i < VPT; i++) {
        p = fmaxf(p, st[i]);
        float v = en[i] * p;
        if (v > bestv2) { bestv2 = v; besti2 = tid * VPT + i; }
    }

    // predicted_start candidate: v1[s] = start[s] * suffixmax_end[s]; descending, '>=' keeps smallest.
    float bestv1 = NEG; int besti1 = 0;
    float q = sm;
    #pragma unroll
    for (int i = VPT - 1; i >= 0; i--) {
        q = fmaxf(q, en[i]);
        float v = st[i] * q;
        if (v >= bestv1) { bestv1 = v; besti1 = tid * VPT + i; }
    }

    // Warp argmax reductions (max value, min index on ties).
    #pragma unroll
    for (int off = 16; off > 0; off >>= 1) {
        float ov1 = __shfl_down_sync(0xffffffffu, bestv1, off);
        int   oi1 = __shfl_down_sync(0xffffffffu, besti1, off);
        if (ov1 > bestv1 || (ov1 == bestv1 && oi1 < besti1)) { bestv1 = ov1; besti1 = oi1; }
        float ov2 = __shfl_down_sync(0xffffffffu, bestv2, off);
        int   oi2 = __shfl_down_sync(0xffffffffu, besti2, off);
        if (ov2 > bestv2 || (ov2 == bestv2 && oi2 < besti2)) { bestv2 = ov2; besti2 = oi2; }
    }

    __shared__ float rv1[NW], rv2[NW];
    __shared__ int   ri1[NW], ri2[NW];
    if (lane == 0) { rv1[wid] = bestv1; ri1[wid] = besti1; rv2[wid] = bestv2; ri2[wid] = besti2; }
    __syncthreads();

    // Warp 0 folds the 32 warp winners with a shuffle reduction.
    if (wid == 0) {
        float v1 = rv1[lane]; int i1 = ri1[lane];
        float v2 = rv2[lane]; int i2 = ri2[lane];
        #pragma unroll
        for (int off = 16; off > 0; off >>= 1) {
            float ov1 = __shfl_down_sync(0xffffffffu, v1, off);
            int   oi1 = __shfl_down_sync(0xffffffffu, i1, off);
            if (ov1 > v1 || (ov1 == v1 && oi1 < i1)) { v1 = ov1; i1 = oi1; }
            float ov2 = __shfl_down_sync(0xffffffffu, v2, off);
            int   oi2 = __shfl_down_sync(0xffffffffu, i2, off);
            if (ov2 > v2 || (ov2 == v2 && oi2 < i2)) { v2 = ov2; i2 = oi2; }
        }
        if (lane == 0) {
            out[b]      = (float)i1;   // predicted_start
            out[SB + b] = (float)i2;   // predicted_end
        }
    }
}

extern "C" void kernel_launch(void* const* d_in, const int* in_sizes, int n_in,
                              void* d_out, int out_size)
{
    const float* start_p = (const float*)d_in[0];
    const float* end_p   = (const float*)d_in[1];
    float* out           = (float*)d_out;
    probs_to_span_kernel<<<SB, NT>>>(start_p, end_p, out);
}

// round 8
// speedup vs baseline: 3.6372x; 1.1535x over previous
#include <cuda_runtime.h>

// Problem: B=16, S=4096.
// predicted_start[b] = argmax_s ( start[b,s] * max_{t>=s} end[b,t] )
// predicted_end[b]   = argmax_t ( end[b,t]   * max_{s<=t} start[b,s] )
// argmax = first occurrence (jnp semantics).
//
// grid = 32: blockIdx.x = 2*b + which. which==0 computes predicted_start,
// which==1 computes predicted_end. Each CTA does ONE scan + ONE argmax.

#define SB  16
#define SS  4096
#define NT  1024
#define VPT 4           // one float4 per array per thread, fully coalesced
#define NW  (NT / 32)   // 32 warps

// WHICH==1 (pred_end):   scan = start (prefix-max, ascending),  mul = end,
//                        ascending argmax with '>' (keeps first).
// WHICH==0 (pred_start): scan = end (suffix-max, descending),   mul = start,
//                        descending argmax with '>=' (keeps smallest index).
template <int WHICH>
__device__ __forceinline__ void span_dir(const float4 s4, const float4 e4,
                                         int tid, int wid, int lane,
                                         float* wT, float* rv, int* ri,
                                         float* __restrict__ out, int b)
{
    const float NEG = -3.0e38f;

    float sc[VPT], mu[VPT];
    if (WHICH) {
        sc[0]=s4.x; sc[1]=s4.y; sc[2]=s4.z; sc[3]=s4.w;
        mu[0]=e4.x; mu[1]=e4.y; mu[2]=e4.z; mu[3]=e4.w;
    } else {
        sc[0]=e4.x; sc[1]=e4.y; sc[2]=e4.z; sc[3]=e4.w;
        mu[0]=s4.x; mu[1]=s4.y; mu[2]=s4.z; mu[3]=s4.w;
    }

    // Chunk max of the scan array.
    float cm = fmaxf(fmaxf(sc[0], sc[1]), fmaxf(sc[2], sc[3]));

    // Warp inclusive scan of chunk maxima (prefix for WHICH=1, suffix for WHICH=0).
    float ws = cm;
    #pragma unroll
    for (int off = 1; off < 32; off <<= 1) {
        if (WHICH) {
            float o = __shfl_up_sync(0xffffffffu, ws, off);
            if (lane >= off) ws = fmaxf(ws, o);
        } else {
            float o = __shfl_down_sync(0xffffffffu, ws, off);
            if (lane + off < 32) ws = fmaxf(ws, o);
        }
    }

    // Publish warp totals (prefix total at lane 31, suffix total at lane 0).
    if (WHICH) { if (lane == 31) wT[wid] = ws; }
    else       { if (lane == 0)  wT[wid] = ws; }
    __syncthreads();

    // Cross-warp exclusive boundary for this warp.
    float wb = NEG;
    #pragma unroll
    for (int w = 0; w < NW; w++) {
        float v = wT[w];
        if (WHICH) { if (w < wid) wb = fmaxf(wb, v); }
        else       { if (w > wid) wb = fmaxf(wb, v); }
    }

    // Exclusive-within-warp boundary.
    float ex;
    if (WHICH) { ex = __shfl_up_sync(0xffffffffu, ws, 1);   if (lane == 0)  ex = NEG; }
    else       { ex = __shfl_down_sync(0xffffffffu, ws, 1); if (lane == 31) ex = NEG; }
    float bound = fmaxf(wb, ex);

    // Per-element running scan * mul, argmax candidate.
    float bestv = NEG; int besti = 0;
    float r = bound;
    if (WHICH) {
        #pragma unroll
        for (int i = 0; i < VPT; i++) {
            r = fmaxf(r, sc[i]);
            float v = mu[i] * r;
            if (v > bestv) { bestv = v; besti = tid * VPT + i; }
        }
    } else {
        #pragma unroll
        for (int i = VPT - 1; i >= 0; i--) {
            r = fmaxf(r, sc[i]);
            float v = mu[i] * r;
            if (v >= bestv) { bestv = v; besti = tid * VPT + i; }
        }
    }

    // Warp argmax (max value, min index on ties).
    #pragma unroll
    for (int off = 16; off > 0; off >>= 1) {
        float ov = __shfl_down_sync(0xffffffffu, bestv, off);
        int   oi = __shfl_down_sync(0xffffffffu, besti, off);
        if (ov > bestv || (ov == bestv && oi < besti)) { bestv = ov; besti = oi; }
    }

    if (lane == 0) { rv[wid] = bestv; ri[wid] = besti; }
    __syncthreads();

    // Warp 0 folds the 32 warp winners.
    if (wid == 0) {
        float v = rv[lane]; int i = ri[lane];
        #pragma unroll
        for (int off = 16; off > 0; off >>= 1) {
            float ov = __shfl_down_sync(0xffffffffu, v, off);
            int   oi = __shfl_down_sync(0xffffffffu, i, off);
            if (ov > v || (ov == v && oi < i)) { v = ov; i = oi; }
        }
        if (lane == 0) {
            if (WHICH) out[SB + b] = (float)i;   // predicted_end
            else       out[b]      = (float)i;   // predicted_start
        }
    }
}

__global__ __launch_bounds__(NT, 1)
void probs_to_span_kernel(const float* __restrict__ start_p,
                          const float* __restrict__ end_p,
                          float* __restrict__ out)
{
    const int bid   = blockIdx.x;
    const int b     = bid >> 1;
    const int which = bid & 1;
    const int tid   = threadIdx.x;
    const int wid   = tid >> 5;
    const int lane  = tid & 31;

    const float4* sp = reinterpret_cast<const float4*>(start_p + (size_t)b * SS);
    const float4* ep = reinterpret_cast<const float4*>(end_p   + (size_t)b * SS);

    // Coalesced loads, both issued before any dependent math.
    float4 s4 = sp[tid];
    float4 e4 = ep[tid];

    __shared__ float wT[NW];
    __shared__ float rv[NW];
    __shared__ int   ri[NW];

    if (which) span_dir<1>(s4, e4, tid, wid, lane, wT, rv, ri, out, b);
    else       span_dir<0>(s4, e4, tid, wid, lane, wT, rv, ri, out, b);
}

extern "C" void kernel_launch(void* const* d_in, const int* in_sizes, int n_in,
                              void* d_out, int out_size)
{
    const float* start_p = (const float*)d_in[0];
    const float* end_p   = (const float*)d_in[1];
    float* out           = (float*)d_out;
    probs_to_span_kernel<<<2 * SB, NT>>>(start_p, end_p, out);
}